// round 4
// baseline (speedup 1.0000x reference)
#include <cuda_runtime.h>
#include <cstdint>

// Problem constants
#define NSEG 6
#define NCH  512
#define NPOS 16384     // 128*128
#define NBINS 16

// ---------------- device scratch (no allocation allowed) ----------------
__device__ unsigned g_mbits[NSEG * 512];     // bit-packed mask, 512 u32/segment
__device__ int      g_posA[NSEG * NBINS];    // bin window start (position)
__device__ int      g_posB[NSEG * NBINS];    // bin window end (exclusive)
__device__ float    g_rdenom[NSEG * NBINS];  // 1/denom per bin
__device__ float    g_ys[NSEG * NCH * NBINS];
__device__ float    g_h1[NSEG * 2048];
__device__ float    g_h2[NSEG * 512];
__device__ float    g_w0[NSEG * 512];

// ---------------- K1: mask + scan + bin boundaries ----------------
// grid = 6 blocks (one per segment), 512 threads, 32 positions/thread.
__global__ void __launch_bounds__(512) k_prep(const int* __restrict__ parsing)
{
    const int s = blockIdx.x;
    const int tid = threadIdx.x;
    __shared__ int ssum[512];
    __shared__ int sstart[NBINS], send[NBINS];

    const int4* __restrict__ pv = (const int4*)(parsing + s * 65536); // [256,256]
    const int base = tid * 32;   // 32 consecutive positions, same h row

    // pass 1: nearest 256->128 is src index*2. int4 covers 2 sampled positions.
    int cnt = 0;
    unsigned mw = 0;
    const int h = base >> 7;
    const int w0 = base & 127;
#pragma unroll
    for (int j = 0; j < 32; j += 2) {
        int w = w0 + j;
        int4 v = pv[h * 128 + (w >> 1)];
        int m0 = (v.x != 0);
        int m1 = (v.z != 0);
        cnt += m0 + m1;
        mw |= ((unsigned)m0) << j;
        mw |= ((unsigned)m1) << (j + 1);
    }
    g_mbits[s * 512 + tid] = mw;

    ssum[tid] = cnt;
    __syncthreads();
    // inclusive Hillis-Steele scan over 512 thread sums
    for (int off = 1; off < 512; off <<= 1) {
        int v = (tid >= off) ? ssum[tid - off] : 0;
        __syncthreads();
        ssum[tid] += v;
        __syncthreads();
    }
    const int incl = ssum[tid];
    const int L    = ssum[511];
    const int exc  = incl - cnt;

    if (tid < NBINS) {
        int k  = tid;
        int st = (k * L) >> 4;                 // floor(k*L/16)
        int en = ((k + 1) * L + 15) >> 4;      // ceil((k+1)*L/16)
        sstart[k] = st;
        send[k]   = en;
        int d = en - st; if (d < 1) d = 1;
        g_rdenom[s * NBINS + k] = 1.0f / (float)d;
        g_posA[s * NBINS + k] = 0;             // default empty window
        g_posB[s * NBINS + k] = 0;
    }
    __syncthreads();

    // pass 2: walk own chunk, assign ranks, record window boundaries.
    int r = exc;
#pragma unroll 1
    for (int j = 0; j < 32; j++) {
        if ((mw >> j) & 1u) {
            int p = base + j;
            for (int k = 0; k < NBINS; k++) {
                if (r == sstart[k])     g_posA[s * NBINS + k] = p;
                if (r + 1 == send[k])   g_posB[s * NBINS + k] = p + 1;
            }
            r++;
        }
    }
}

// ---------------- K2: masked adaptive pool ----------------
// grid = NSEG*NCH blocks, 512 threads = 16 warps; warp k owns bin k.
__global__ void __launch_bounds__(512) k_pool(const float* __restrict__ xs)
{
    const int sc   = blockIdx.x;          // s*512 + c
    const int s    = sc >> 9;
    const int warp = threadIdx.x >> 5;
    const int lane = threadIdx.x & 31;

    const int lo = g_posA[s * NBINS + warp];
    const int hi = g_posB[s * NBINS + warp];

    const float4* __restrict__ x4 = (const float4*)(xs + ((size_t)sc << 14));
    const unsigned* __restrict__ mb = g_mbits + s * 512;

    float a0 = 0.f, a1 = 0.f;
    const int i1 = (hi + 3) >> 2;
    int i = (lo >> 2) + lane;
    // 2-way manual unroll: 2 independent LDG.128 in flight per thread
    for (; i + 32 < i1; i += 64) {
        float4 va = x4[i];
        float4 vb = x4[i + 32];
        unsigned na = mb[i >> 3] >> ((i & 7) << 2);
        unsigned nc = mb[(i + 32) >> 3] >> (((i + 32) & 7) << 2);
        int pa = i << 2, pb = (i + 32) << 2;
        a0 += ((na & 1u) && pa     >= lo && pa     < hi) ? va.x : 0.f;
        a1 += ((na & 2u) && pa + 1 >= lo && pa + 1 < hi) ? va.y : 0.f;
        a0 += ((na & 4u) && pa + 2 >= lo && pa + 2 < hi) ? va.z : 0.f;
        a1 += ((na & 8u) && pa + 3 >= lo && pa + 3 < hi) ? va.w : 0.f;
        a0 += ((nc & 1u) && pb     >= lo && pb     < hi) ? vb.x : 0.f;
        a1 += ((nc & 2u) && pb + 1 >= lo && pb + 1 < hi) ? vb.y : 0.f;
        a0 += ((nc & 4u) && pb + 2 >= lo && pb + 2 < hi) ? vb.z : 0.f;
        a1 += ((nc & 8u) && pb + 3 >= lo && pb + 3 < hi) ? vb.w : 0.f;
    }
    if (i < i1) {
        float4 v = x4[i];
        unsigned nib = mb[i >> 3] >> ((i & 7) << 2);
        int pb = i << 2;
        a0 += ((nib & 1u) && pb     >= lo && pb     < hi) ? v.x : 0.f;
        a1 += ((nib & 2u) && pb + 1 >= lo && pb + 1 < hi) ? v.y : 0.f;
        a0 += ((nib & 4u) && pb + 2 >= lo && pb + 2 < hi) ? v.z : 0.f;
        a1 += ((nib & 8u) && pb + 3 >= lo && pb + 3 < hi) ? v.w : 0.f;
    }
    float acc = a0 + a1;
#pragma unroll
    for (int o = 16; o; o >>= 1) acc += __shfl_xor_sync(0xffffffffu, acc, o);
    if (lane == 0) {
        int c = sc & 511;
        g_ys[s * (NCH * NBINS) + c * NBINS + warp] = acc * g_rdenom[s * NBINS + warp];
    }
}

// ---------------- generic warp-per-row GEMV, MLP=U ----------------
__device__ __forceinline__ float dot4(float4 a, float4 b, float acc)
{
    acc = fmaf(a.x, b.x, acc);
    acc = fmaf(a.y, b.y, acc);
    acc = fmaf(a.z, b.z, acc);
    acc = fmaf(a.w, b.w, acc);
    return acc;
}

template <int ROWS, int KLEN, int U>
__device__ __forceinline__ void gemv_body(const float* __restrict__ W,
                                          const float* __restrict__ bias,
                                          const float* __restrict__ x,
                                          float* __restrict__ y,
                                          float* __restrict__ out2, int out2off)
{
    __shared__ float4 sx[KLEN / 4];
    constexpr int BPS = ROWS / 8;             // 8 warps per 256-thread block
    constexpr int K4  = KLEN / 4;
    constexpr int STEP = 32 * U;
    constexpr int ITERS = K4 / STEP;
    static_assert(K4 % STEP == 0, "K tile");
    const int s        = blockIdx.x / BPS;
    const int rowInSeg = (blockIdx.x % BPS) * 8 + (threadIdx.x >> 5);
    const int lane     = threadIdx.x & 31;

    const float4* __restrict__ xv = (const float4*)(x + s * KLEN);
    for (int i = threadIdx.x; i < K4; i += 256) sx[i] = xv[i];
    __syncthreads();

    const float4* __restrict__ wv = (const float4*)(W + (size_t)(s * ROWS + rowInSeg) * KLEN);

    float acc[U];
#pragma unroll
    for (int u = 0; u < U; u++) acc[u] = 0.f;

#pragma unroll 1
    for (int t = 0; t < ITERS; t++) {
        const int b = t * STEP + lane;
        float4 w[U];
#pragma unroll
        for (int u = 0; u < U; u++) w[u] = wv[b + 32 * u];   // U LDG.128 in flight
#pragma unroll
        for (int u = 0; u < U; u++) acc[u] = dot4(w[u], sx[b + 32 * u], acc[u]);
    }

    float a = 0.f;
#pragma unroll
    for (int u = 0; u < U; u++) a += acc[u];
#pragma unroll
    for (int o = 16; o; o >>= 1) a += __shfl_xor_sync(0xffffffffu, a, o);

    if (lane == 0) {
        float r = a + bias[s * ROWS + rowInSeg];
        y[s * ROWS + rowInSeg] = r;
        if (out2) out2[s * 960 + out2off + rowInSeg] = r;
    }
}

__global__ void __launch_bounds__(256) k_fcA(const float* __restrict__ W, const float* __restrict__ b)
{ gemv_body<2048, 8192, 8>(W, b, g_ys, g_h1, nullptr, 0); }

__global__ void __launch_bounds__(256) k_fcB(const float* __restrict__ W, const float* __restrict__ b)
{ gemv_body<512, 2048, 8>(W, b, g_h1, g_h2, nullptr, 0); }

__global__ void __launch_bounds__(256) k_fcC(const float* __restrict__ W, const float* __restrict__ b, float* out)
{ gemv_body<512, 512, 4>(W, b, g_h2, g_w0, out, 0); }

// ---------------- tail: p1 -> p2 -> p3 fused, 6 blocks (one per segment) ----
__device__ __forceinline__ void tail_layer(const float* __restrict__ W,
                                           const float* __restrict__ bias,
                                           const float* __restrict__ xsm,
                                           float* __restrict__ ysm,
                                           float* __restrict__ out, int rows, int klen,
                                           int wid, int lane)
{
    const int k4 = klen >> 2;
    const int f4 = k4 >> 5;                   // float4s per lane (4/2/1)
    for (int row = wid; row < rows; row += 8) {
        const float4* wr = (const float4*)(W + (size_t)row * klen);
        const float4* xr = (const float4*)xsm;
        float a = 0.f;
        for (int i = lane; i < k4; i += 32) a = dot4(wr[i], xr[i], a);
        (void)f4;
#pragma unroll
        for (int o = 16; o; o >>= 1) a += __shfl_xor_sync(0xffffffffu, a, o);
        if (lane == 0) {
            float r = a + bias[row];
            if (ysm) ysm[row] = r;
            out[row] = r;
        }
    }
}

__global__ void __launch_bounds__(256) k_tail(
    const float* __restrict__ p1w, const float* __restrict__ p1b,
    const float* __restrict__ p2w, const float* __restrict__ p2b,
    const float* __restrict__ p3w, const float* __restrict__ p3b,
    float* __restrict__ out)
{
    const int s = blockIdx.x;
    const int wid = threadIdx.x >> 5;
    const int lane = threadIdx.x & 31;
    __shared__ float sw0[512], sw1[256], sw2[128];

    for (int i = threadIdx.x; i < 512; i += 256) sw0[i] = g_w0[s * 512 + i];
    __syncthreads();
    tail_layer(p1w, p1b, sw0, sw1, out + s * 960 + 512, 256, 512, wid, lane);
    __syncthreads();
    tail_layer(p2w, p2b, sw1, sw2, out + s * 960 + 768, 128, 256, wid, lane);
    __syncthreads();
    tail_layer(p3w, p3b, sw2, nullptr, out + s * 960 + 896, 64, 128, wid, lane);
}

// ---------------- launch ----------------
extern "C" void kernel_launch(void* const* d_in, const int* in_sizes, int n_in,
                              void* d_out, int out_size)
{
    const float* xs      = (const float*)d_in[0];
    const int*   parsing = (const int*)  d_in[1];
    const float* fcA_w   = (const float*)d_in[2];
    const float* fcA_b   = (const float*)d_in[3];
    const float* fcB_w   = (const float*)d_in[4];
    const float* fcB_b   = (const float*)d_in[5];
    const float* fcC_w   = (const float*)d_in[6];
    const float* fcC_b   = (const float*)d_in[7];
    const float* p1_w    = (const float*)d_in[8];
    const float* p1_b    = (const float*)d_in[9];
    const float* p2_w    = (const float*)d_in[10];
    const float* p2_b    = (const float*)d_in[11];
    const float* p3_w    = (const float*)d_in[12];
    const float* p3_b    = (const float*)d_in[13];
    float* out = (float*)d_out;

    k_prep<<<NSEG, 512>>>(parsing);
    k_pool<<<NSEG * NCH, 512>>>(xs);
    k_fcA <<<NSEG * (2048 / 8), 256>>>(fcA_w, fcA_b);
    k_fcB <<<NSEG * (512  / 8), 256>>>(fcB_w, fcB_b);
    k_fcC <<<NSEG * (512  / 8), 256>>>(fcC_w, fcC_b, out);
    k_tail<<<NSEG, 256>>>(p1_w, p1_b, p2_w, p2_b, p3_w, p3_b, out);
}